// round 2
// baseline (speedup 1.0000x reference)
#include <cuda_runtime.h>
#include <cstdint>
#include <cstdio>

#define NB   2
#define NN   50000
#define HH   64
#define NE   1000000
#define NOBS 128
#define NA   18
#define NAFF 512
#define NEFF 256

typedef unsigned long long ull;

// ---------------- device scratch ----------------
__device__ float g_xpair[(size_t)NN * 256];   // [n][k][2] interleaved batch pairs, 51.2 MB
__device__ float g_Wp[128 * 128];             // fused weight
__device__ float g_projG[NB * HH];
__device__ float g_projC[NB * HH];
__device__ int   g_flag[NN];
__device__ int   g_cnt[NN];
__device__ int   g_off[NN + 1];
__device__ int   g_cur[NN];
__device__ int   g_esrc[NE];

// ---------------- small helpers ----------------
__device__ __forceinline__ void fma2(ull& d, ull a, ull b) {
    asm("fma.rn.f32x2 %0, %1, %2, %0;" : "+l"(d) : "l"(a), "l"(b));
}
__device__ __forceinline__ ull splat2(float w) {
    ull r; unsigned u = __float_as_uint(w);
    asm("mov.b64 %0, {%1, %1};" : "=l"(r) : "r"(u));
    return r;
}
__device__ __forceinline__ float2 u2f2(ull v) {
    float2 f;
    f.x = __uint_as_float((unsigned)v);
    f.y = __uint_as_float((unsigned)(v >> 32));
    return f;
}
__device__ __forceinline__ void cpa16(void* dst, const void* src) {
    unsigned d = (unsigned)__cvta_generic_to_shared(dst);
    asm volatile("cp.async.cg.shared.global [%0], [%1], 16;" :: "r"(d), "l"(src));
}

// ---------------- K1a: projections + flags ----------------
__global__ void prep_small_kernel(const float* __restrict__ obs,
                                  const float* __restrict__ W_in,
                                  const float* __restrict__ b_in,
                                  const float* __restrict__ W_gate,
                                  const float* __restrict__ W_cand,
                                  const int* __restrict__ afferent_idx) {
    __shared__ float proj[NB * HH];
    int t = threadIdx.x;            // 128 threads
    int b = t >> 6, h = t & 63;
    float acc = b_in[h];
    for (int o = 0; o < NOBS; o++)
        acc += obs[b * NOBS + o] * W_in[o * HH + h];
    proj[b * HH + h] = acc;
    __syncthreads();
    float ag = 0.f, ac = 0.f;
    for (int k = 0; k < HH; k++) {
        float p = proj[b * HH + k];
        ag += p * W_gate[(HH + k) * HH + h];
        ac += p * W_cand[(HH + k) * HH + h];
    }
    g_projG[b * HH + h] = ag;
    g_projC[b * HH + h] = ac;
    for (int i = t; i < NAFF; i += 128)
        g_flag[afferent_idx[i]] = 1;
}

// ---------------- K1b: fused weight W' ----------------
__global__ void prep_W_kernel(const float* __restrict__ W_msg,
                              const float* __restrict__ W_gate,
                              const float* __restrict__ W_cand) {
    int c = blockIdx.x;     // output column 0..127
    int k = threadIdx.x;    // input row 0..127
    float w;
    if (k < HH) {
        w = (c < HH) ? W_gate[k * HH + c] : W_cand[k * HH + (c - HH)];
    } else {
        int km = k - HH;
        float acc = 0.f;
        if (c < HH) {
            for (int t = 0; t < HH; t++)
                acc += W_msg[km * HH + t] * W_gate[(HH + t) * HH + c];
        } else {
            for (int t = 0; t < HH; t++)
                acc += W_msg[km * HH + t] * W_cand[(HH + t) * HH + (c - HH)];
        }
        w = acc;
    }
    g_Wp[k * 128 + c] = w;
}

// ---------------- CSR build ----------------
__global__ void hist_kernel(const int* __restrict__ dst) {
    int i = blockIdx.x * blockDim.x + threadIdx.x;
    if (i < NE) atomicAdd(&g_cnt[dst[i]], 1);
}

__global__ void scan_kernel() {   // 1 block, 1024 threads
    __shared__ int sums[1024];
    int t = threadIdx.x;
    const int C = (NN + 1023) / 1024;   // 49
    int base = t * C;
    int s = 0;
    for (int i = 0; i < C; i++) {
        int idx = base + i;
        if (idx < NN) s += g_cnt[idx];
    }
    sums[t] = s;
    __syncthreads();
    for (int d = 1; d < 1024; d <<= 1) {
        int v = (t >= d) ? sums[t - d] : 0;
        __syncthreads();
        sums[t] += v;
        __syncthreads();
    }
    int off = (t == 0) ? 0 : sums[t - 1];
    for (int i = 0; i < C; i++) {
        int idx = base + i;
        if (idx < NN) {
            g_off[idx] = off;
            g_cur[idx] = off;
            off += g_cnt[idx];
        }
    }
    if (t == 1023) g_off[NN] = NE;
}

__global__ void scatter_kernel(const int* __restrict__ src,
                               const int* __restrict__ dst) {
    int i = blockIdx.x * blockDim.x + threadIdx.x;
    if (i < NE) {
        int d = dst[i];
        int pos = atomicAdd(&g_cur[d], 1);
        g_esrc[pos] = src[i];
    }
}

// ---------------- K2: CSR aggregate + batch-pair interleave ----------------
// One warp per dst node. Lane l owns k = {2l, 2l+1} for both batches.
__global__ void __launch_bounds__(256) agg_kernel(const float* __restrict__ state) {
    int warp = (blockIdx.x * 256 + threadIdx.x) >> 5;
    if (warp >= NN) return;
    int lane = threadIdx.x & 31;
    int n = warp;
    int beg = g_off[n], end = g_off[n + 1];
    const float2* s0 = (const float2*)state;       // batch0 float2 view
    const float2* s1 = s0 + (size_t)NN * 32;       // batch1
    float4 acc = make_float4(0.f, 0.f, 0.f, 0.f);
    for (int j = beg; j < end; j++) {
        int src = __ldg(g_esrc + j);
        float2 a = __ldg(s0 + (size_t)src * 32 + lane);
        float2 b = __ldg(s1 + (size_t)src * 32 + lane);
        acc.x += a.x; acc.y += a.y; acc.z += b.x; acc.w += b.y;
    }
    float2 sa = __ldg(s0 + (size_t)n * 32 + lane);
    float2 sb = __ldg(s1 + (size_t)n * 32 + lane);
    float* xp = g_xpair + (size_t)n * 256;
    // state half: k = 2l, 2l+1 -> pairs {sa.x,sb.x},{sa.y,sb.y}
    ((float4*)xp)[lane] = make_float4(sa.x, sb.x, sa.y, sb.y);
    // agg half: k = 64+2l, 64+2l+1 -> pairs {acc.x,acc.z},{acc.y,acc.w}
    ((float4*)(xp + 128))[lane] = make_float4(acc.x, acc.z, acc.y, acc.w);
}

// ---------------- K3: f32x2 register-tiled GEMM + GRU epilogue ----------------
// X = [s | agg] pairs (50000 x 128 x f32x2) @ W'(128x128); tile: 48 nodes/block.
// thread: g = tid&31 -> cols 4g..4g+3 ; p = tid>>5 -> node-pairs p*6..p*6+5.
#define TILE_N 48
#define XS_ULL (TILE_N * 128)     // 6144 ull per buffer

__global__ void __launch_bounds__(256) gemm_kernel(const float* __restrict__ b_gate,
                                                   const float* __restrict__ b_cand,
                                                   float* __restrict__ out_ns) {
    extern __shared__ float smem[];
    float* Ws = smem;                                   // 16384 floats (64KB)
    ull* xs = (ull*)(smem + 16384);                     // 2 * 6144 ull (96KB)
    float* bg = (float*)(xs + 2 * XS_ULL);              // 64
    float* bc = bg + 64;                                // 64
    float* pg = bc + 64;                                // 128
    float* pc = pg + 128;                               // 128

    int tid = threadIdx.x;
    for (int i = tid; i < 16384 / 4; i += 256)
        ((float4*)Ws)[i] = ((const float4*)g_Wp)[i];
    if (tid < 64) { bg[tid] = b_gate[tid]; bc[tid] = b_cand[tid]; }
    if (tid < 128) { pg[tid] = g_projG[tid]; pc[tid] = g_projC[tid]; }

    int g = tid & 31, p = tid >> 5;
    const int numTiles = (NN + TILE_N - 1) / TILE_N;    // 1042

    // prefetch first tile
    int it0 = blockIdx.x;
    {
        int nb = it0 * TILE_N;
        for (int c = tid; c < TILE_N * 64; c += 256) {  // 64 x 16B chunks per node
            int node = nb + (c >> 6);
            int off = c & 63;
            int nn = node < NN ? node : 0;
            cpa16((char*)xs + (size_t)c * 16,
                  (const char*)(g_xpair + (size_t)nn * 256) + off * 16);
        }
    }
    asm volatile("cp.async.commit_group;" ::: "memory");

    int ib = 0;
    for (int it = it0; it < numTiles; it += gridDim.x, ib ^= 1) {
        asm volatile("cp.async.wait_group 0;" ::: "memory");
        __syncthreads();
        int nxt = it + gridDim.x;
        if (nxt < numTiles) {
            ull* dstb = xs + (ib ^ 1) * XS_ULL;
            int nb = nxt * TILE_N;
            for (int c = tid; c < TILE_N * 64; c += 256) {
                int node = nb + (c >> 6);
                int off = c & 63;
                int nn = node < NN ? node : 0;
                cpa16((char*)dstb + (size_t)c * 16,
                      (const char*)(g_xpair + (size_t)nn * 256) + off * 16);
            }
        }
        asm volatile("cp.async.commit_group;" ::: "memory");

        ull* xb = xs + ib * XS_ULL;
        const ull* xr0 = xb + (p * 6 + 0) * 128;
        const ull* xr1 = xb + (p * 6 + 1) * 128;
        const ull* xr2 = xb + (p * 6 + 2) * 128;
        const ull* xr3 = xb + (p * 6 + 3) * 128;
        const ull* xr4 = xb + (p * 6 + 4) * 128;
        const ull* xr5 = xb + (p * 6 + 5) * 128;

        ull acc[6][4];
#pragma unroll
        for (int m = 0; m < 6; m++)
#pragma unroll
            for (int c = 0; c < 4; c++) acc[m][c] = 0ull;

#pragma unroll 4
        for (int k = 0; k < 128; k++) {
            float4 w = ((const float4*)(Ws + k * 128))[g];
            ull w0 = splat2(w.x), w1 = splat2(w.y), w2 = splat2(w.z), w3 = splat2(w.w);
            ull x0 = xr0[k], x1 = xr1[k], x2 = xr2[k],
                x3 = xr3[k], x4 = xr4[k], x5 = xr5[k];
            fma2(acc[0][0], w0, x0); fma2(acc[0][1], w1, x0); fma2(acc[0][2], w2, x0); fma2(acc[0][3], w3, x0);
            fma2(acc[1][0], w0, x1); fma2(acc[1][1], w1, x1); fma2(acc[1][2], w2, x1); fma2(acc[1][3], w3, x1);
            fma2(acc[2][0], w0, x2); fma2(acc[2][1], w1, x2); fma2(acc[2][2], w2, x2); fma2(acc[2][3], w3, x2);
            fma2(acc[3][0], w0, x3); fma2(acc[3][1], w1, x3); fma2(acc[3][2], w2, x3); fma2(acc[3][3], w3, x3);
            fma2(acc[4][0], w0, x4); fma2(acc[4][1], w1, x4); fma2(acc[4][2], w2, x4); fma2(acc[4][3], w3, x4);
            fma2(acc[5][0], w0, x5); fma2(acc[5][1], w1, x5); fma2(acc[5][2], w2, x5); fma2(acc[5][3], w3, x5);
        }

        // epilogue: lane g<16 holds z-pre for cols 4g..4g+3; partner g+16 holds cand-pre
        int nb = it * TILE_N;
        const ull* xrs[6] = {xr0, xr1, xr2, xr3, xr4, xr5};
#pragma unroll
        for (int m = 0; m < 6; m++) {
            ull o0 = __shfl_xor_sync(0xffffffffu, acc[m][0], 16);
            ull o1 = __shfl_xor_sync(0xffffffffu, acc[m][1], 16);
            ull o2 = __shfl_xor_sync(0xffffffffu, acc[m][2], 16);
            ull o3 = __shfl_xor_sync(0xffffffffu, acc[m][3], 16);
            int n = nb + p * 6 + m;
            if (g < 16 && n < NN) {
                int fl = g_flag[n];
                ull zacc[4] = {acc[m][0], acc[m][1], acc[m][2], acc[m][3]};
                ull cacc[4] = {o0, o1, o2, o3};
                float4 r0, r1;
                float* q0 = (float*)&r0;
                float* q1 = (float*)&r1;
#pragma unroll
                for (int c = 0; c < 4; c++) {
                    int col = 4 * g + c;
                    float2 zp = u2f2(zacc[c]);
                    float2 cp = u2f2(cacc[c]);
                    float2 sp = u2f2(xrs[m][col]);       // col < 64: state pair
                    float zb0 = zp.x + bg[col] + (fl ? pg[col] : 0.f);
                    float zb1 = zp.y + bg[col] + (fl ? pg[64 + col] : 0.f);
                    float cb0 = cp.x + bc[col] + (fl ? pc[col] : 0.f);
                    float cb1 = cp.y + bc[col] + (fl ? pc[64 + col] : 0.f);
                    float z0 = __fdividef(1.f, 1.f + __expf(-zb0));
                    float z1 = __fdividef(1.f, 1.f + __expf(-zb1));
                    float t0 = 1.f - __fdividef(2.f, __expf(2.f * cb0) + 1.f);
                    float t1 = 1.f - __fdividef(2.f, __expf(2.f * cb1) + 1.f);
                    q0[c] = fmaf(z0, t0 - sp.x, sp.x);
                    q1[c] = fmaf(z1, t1 - sp.y, sp.y);
                }
                *((float4*)(out_ns + (size_t)n * 64 + 4 * g)) = r0;
                *((float4*)(out_ns + ((size_t)NN + n) * 64 + 4 * g)) = r1;
            }
        }
    }
}

// ---------------- K4: readout + policy heads ----------------
__global__ void readout_kernel(const float* __restrict__ ns,
                               const int* __restrict__ efferent_idx,
                               const float* __restrict__ W_dec,
                               const float* __restrict__ b_dec,
                               const float* __restrict__ W_mean,
                               const float* __restrict__ b_mean,
                               const float* __restrict__ W_ls,
                               const float* __restrict__ b_ls,
                               float* __restrict__ out) {
    __shared__ float ro[NB * HH];
    __shared__ float dec[NB * HH];
    int t = threadIdx.x;    // 128 threads
    int b = t >> 6, h = t & 63;
    float sum = 0.f;
    for (int i = 0; i < NEFF; i++) {
        int idx = efferent_idx[i];
        sum += ns[((size_t)b * NN + idx) * HH + h];
    }
    ro[b * HH + h] = sum * (1.f / NEFF);
    __syncthreads();
    float acc = b_dec[h];
    for (int k = 0; k < HH; k++)
        acc += ro[b * HH + k] * W_dec[k * HH + h];
    dec[b * HH + h] = tanhf(acc);
    __syncthreads();
    if (t < NB * NA) {
        int bb = t / NA, a = t % NA;
        float m = b_mean[a], ls = b_ls[a];
        for (int k = 0; k < HH; k++) {
            float d = dec[bb * HH + k];
            m  += d * W_mean[k * NA + a];
            ls += d * W_ls[k * NA + a];
        }
        ls = fminf(fmaxf(ls, -5.f), 2.f);
        out[bb * NA + a] = m;
        out[NB * NA + bb * NA + a] = ls;
    }
}

// ---------------- launch ----------------
extern "C" void kernel_launch(void* const* d_in, const int* in_sizes, int n_in,
                              void* d_out, int out_size) {
    const float* obs    = (const float*)d_in[0];
    const float* state  = (const float*)d_in[1];
    const float* W_in   = (const float*)d_in[2];
    const float* b_in   = (const float*)d_in[3];
    const float* W_msg  = (const float*)d_in[4];
    const float* W_gate = (const float*)d_in[5];
    const float* b_gate = (const float*)d_in[6];
    const float* W_cand = (const float*)d_in[7];
    const float* b_cand = (const float*)d_in[8];
    const float* W_dec  = (const float*)d_in[9];
    const float* b_dec  = (const float*)d_in[10];
    const float* W_mean = (const float*)d_in[11];
    const float* b_mean = (const float*)d_in[12];
    const float* W_ls   = (const float*)d_in[13];
    const float* b_ls   = (const float*)d_in[14];
    const int* src_idx  = (const int*)d_in[15];
    const int* dst_idx  = (const int*)d_in[16];
    const int* aff_idx  = (const int*)d_in[17];
    const int* eff_idx  = (const int*)d_in[18];
    float* out = (float*)d_out;
    float* out_ns = out + 2 * NB * NA;

    void *cntp = nullptr, *flagp = nullptr;
    cudaGetSymbolAddress(&cntp, g_cnt);
    cudaGetSymbolAddress(&flagp, g_flag);
    cudaMemsetAsync(cntp, 0, sizeof(int) * NN);
    cudaMemsetAsync(flagp, 0, sizeof(int) * NN);

    prep_small_kernel<<<1, 128>>>(obs, W_in, b_in, W_gate, W_cand, aff_idx);
    prep_W_kernel<<<128, 128>>>(W_msg, W_gate, W_cand);

    hist_kernel<<<(NE + 255) / 256, 256>>>(dst_idx);
    scan_kernel<<<1, 1024>>>();
    scatter_kernel<<<(NE + 255) / 256, 256>>>(src_idx, dst_idx);
    agg_kernel<<<(NN * 32 + 255) / 256, 256>>>(state);

    size_t smem = 16384u * 4 + 2u * XS_ULL * 8 + 384u * 4;   // 165376 bytes
    cudaFuncSetAttribute(gemm_kernel, cudaFuncAttributeMaxDynamicSharedMemorySize, (int)smem);
    gemm_kernel<<<148, 256, smem>>>(b_gate, b_cand, out_ns);

    readout_kernel<<<1, 128>>>(out_ns, eff_idx, W_dec, b_dec, W_mean, b_mean, W_ls, b_ls, out);
}

// round 4
// speedup vs baseline: 1.3377x; 1.3377x over previous
#include <cuda_runtime.h>
#include <cstdint>
#include <cstdio>

#define NB   2
#define NN   50000
#define HH   64
#define NE   1000000
#define NOBS 128
#define NA   18
#define NAFF 512
#define NEFF 256
#define PB   196

typedef unsigned long long ull;

// ---------------- device scratch ----------------
__device__ float g_xpair[(size_t)NN * 256];   // [n][k][2] batch-pair interleave, 51.2 MB
__device__ float g_Wp[128 * 128];             // fused weight
__device__ float g_projG[NB * HH];
__device__ float g_projC[NB * HH];
__device__ int   g_flag[NN];
__device__ int   g_cnt[NN];
__device__ int   g_off[NN + 1];
__device__ int   g_cur[NN];
__device__ int   g_esrc[NE];
__device__ int   g_part[256];
__device__ int   g_base[256];

// ---------------- helpers ----------------
__device__ __forceinline__ void fma2(ull& d, ull a, ull b) {
    asm("fma.rn.f32x2 %0, %1, %2, %0;" : "+l"(d) : "l"(a), "l"(b));
}
__device__ __forceinline__ ull splat2(float w) {
    ull r; unsigned u = __float_as_uint(w);
    asm("mov.b64 %0, {%1, %1};" : "=l"(r) : "r"(u));
    return r;
}
__device__ __forceinline__ float2 u2f2(ull v) {
    float2 f;
    f.x = __uint_as_float((unsigned)v);
    f.y = __uint_as_float((unsigned)(v >> 32));
    return f;
}
__device__ __forceinline__ void cpa16(void* dst, const void* src) {
    unsigned d = (unsigned)__cvta_generic_to_shared(dst);
    asm volatile("cp.async.cg.shared.global [%0], [%1], 16;" :: "r"(d), "l"(src));
}
__device__ __forceinline__ int warp_incl_scan(int v) {
    int lane = threadIdx.x & 31;
#pragma unroll
    for (int d = 1; d < 32; d <<= 1) {
        int t = __shfl_up_sync(0xffffffffu, v, d);
        if (lane >= d) v += t;
    }
    return v;
}

// ---------------- K1a: projections + flags ----------------
__global__ void prep_small_kernel(const float* __restrict__ obs,
                                  const float* __restrict__ W_in,
                                  const float* __restrict__ b_in,
                                  const float* __restrict__ W_gate,
                                  const float* __restrict__ W_cand,
                                  const int* __restrict__ afferent_idx) {
    __shared__ float proj[NB * HH];
    int t = threadIdx.x;            // 128 threads
    int b = t >> 6, h = t & 63;
    float acc = b_in[h];
    for (int o = 0; o < NOBS; o++)
        acc += obs[b * NOBS + o] * W_in[o * HH + h];
    proj[b * HH + h] = acc;
    __syncthreads();
    float ag = 0.f, ac = 0.f;
    for (int k = 0; k < HH; k++) {
        float p = proj[b * HH + k];
        ag += p * W_gate[(HH + k) * HH + h];
        ac += p * W_cand[(HH + k) * HH + h];
    }
    g_projG[b * HH + h] = ag;
    g_projC[b * HH + h] = ac;
    for (int i = t; i < NAFF; i += 128)
        g_flag[afferent_idx[i]] = 1;
}

// ---------------- K1b: fused weight W' ----------------
__global__ void prep_W_kernel(const float* __restrict__ W_msg,
                              const float* __restrict__ W_gate,
                              const float* __restrict__ W_cand) {
    int c = blockIdx.x;     // output column 0..127
    int k = threadIdx.x;    // input row 0..127
    float w;
    if (k < HH) {
        w = (c < HH) ? W_gate[k * HH + c] : W_cand[k * HH + (c - HH)];
    } else {
        int km = k - HH;
        float acc = 0.f;
        if (c < HH) {
            for (int t = 0; t < HH; t++)
                acc += W_msg[km * HH + t] * W_gate[(HH + t) * HH + c];
        } else {
            for (int t = 0; t < HH; t++)
                acc += W_msg[km * HH + t] * W_cand[(HH + t) * HH + (c - HH)];
        }
        w = acc;
    }
    g_Wp[k * 128 + c] = w;
}

// ---------------- CSR build ----------------
__global__ void hist_kernel(const int4* __restrict__ dst4) {
    int i = blockIdx.x * blockDim.x + threadIdx.x;
    if (i < NE / 4) {
        int4 d = __ldg(dst4 + i);
        atomicAdd(&g_cnt[d.x], 1);
        atomicAdd(&g_cnt[d.y], 1);
        atomicAdd(&g_cnt[d.z], 1);
        atomicAdd(&g_cnt[d.w], 1);
    }
}

__global__ void scan_part_kernel() {       // grid PB, block 256
    int i = blockIdx.x * 256 + threadIdx.x;
    int v = (i < NN) ? g_cnt[i] : 0;
    __shared__ int ws[8];
    int s = v;
#pragma unroll
    for (int d = 16; d > 0; d >>= 1) s += __shfl_down_sync(0xffffffffu, s, d);
    if ((threadIdx.x & 31) == 0) ws[threadIdx.x >> 5] = s;
    __syncthreads();
    if (threadIdx.x == 0) {
        int tot = 0;
        for (int w = 0; w < 8; w++) tot += ws[w];
        g_part[blockIdx.x] = tot;
    }
}

__global__ void scan_mid_kernel() {        // 1 block, 256 threads
    int t = threadIdx.x;
    int lane = t & 31, w = t >> 5;
    int v = (t < PB) ? g_part[t] : 0;
    int inc = warp_incl_scan(v);
    __shared__ int ws[8];
    if (lane == 31) ws[w] = inc;
    __syncthreads();
    if (w == 0) {
        int q = (lane < 8) ? ws[lane] : 0;
        int qi = warp_incl_scan(q);
        if (lane < 8) ws[lane] = qi;
    }
    __syncthreads();
    int base = (w > 0) ? ws[w - 1] : 0;
    if (t < 256) g_base[t] = base + inc - v;   // exclusive
}

__global__ void scan_final_kernel() {      // grid PB, block 256
    int i = blockIdx.x * 256 + threadIdx.x;
    int t = threadIdx.x;
    int lane = t & 31, w = t >> 5;
    int v = (i < NN) ? g_cnt[i] : 0;
    int inc = warp_incl_scan(v);
    __shared__ int ws[8];
    if (lane == 31) ws[w] = inc;
    __syncthreads();
    if (w == 0) {
        int q = (lane < 8) ? ws[lane] : 0;
        int qi = warp_incl_scan(q);
        if (lane < 8) ws[lane] = qi;
    }
    __syncthreads();
    int base = (w > 0) ? ws[w - 1] : 0;
    int off = g_base[blockIdx.x] + base + inc - v;
    if (i < NN) { g_off[i] = off; g_cur[i] = off; }
    if (i == 0) g_off[NN] = NE;
}

__global__ void scatter_kernel(const int4* __restrict__ src4,
                               const int4* __restrict__ dst4) {
    int i = blockIdx.x * blockDim.x + threadIdx.x;
    if (i < NE / 4) {
        int4 s = __ldg(src4 + i);
        int4 d = __ldg(dst4 + i);
        g_esrc[atomicAdd(&g_cur[d.x], 1)] = s.x;
        g_esrc[atomicAdd(&g_cur[d.y], 1)] = s.y;
        g_esrc[atomicAdd(&g_cur[d.z], 1)] = s.z;
        g_esrc[atomicAdd(&g_cur[d.w], 1)] = s.w;
    }
}

// ---------------- K2: CSR aggregate + batch-pair interleave ----------------
__global__ void __launch_bounds__(256) agg_kernel(const float* __restrict__ state) {
    int warp = (blockIdx.x * 256 + threadIdx.x) >> 5;
    if (warp >= NN) return;
    int lane = threadIdx.x & 31;
    int n = warp;
    int beg = g_off[n], end = g_off[n + 1];
    const float2* s0 = (const float2*)state;
    const float2* s1 = s0 + (size_t)NN * 32;
    float4 acc = make_float4(0.f, 0.f, 0.f, 0.f);
    int j = beg;
    for (; j + 2 <= end; j += 2) {
        int e0 = __ldg(g_esrc + j), e1 = __ldg(g_esrc + j + 1);
        float2 a0 = __ldg(s0 + (size_t)e0 * 32 + lane);
        float2 b0 = __ldg(s1 + (size_t)e0 * 32 + lane);
        float2 a1 = __ldg(s0 + (size_t)e1 * 32 + lane);
        float2 b1 = __ldg(s1 + (size_t)e1 * 32 + lane);
        acc.x += a0.x + a1.x; acc.y += a0.y + a1.y;
        acc.z += b0.x + b1.x; acc.w += b0.y + b1.y;
    }
    for (; j < end; j++) {
        int e0 = __ldg(g_esrc + j);
        float2 a = __ldg(s0 + (size_t)e0 * 32 + lane);
        float2 b = __ldg(s1 + (size_t)e0 * 32 + lane);
        acc.x += a.x; acc.y += a.y; acc.z += b.x; acc.w += b.y;
    }
    float2 sa = __ldg(s0 + (size_t)n * 32 + lane);
    float2 sb = __ldg(s1 + (size_t)n * 32 + lane);
    float* xp = g_xpair + (size_t)n * 256;
    ((float4*)xp)[lane] = make_float4(sa.x, sb.x, sa.y, sb.y);
    ((float4*)(xp + 128))[lane] = make_float4(acc.x, acc.z, acc.y, acc.w);
}

// ---------------- K3: f32x2 register-tiled GEMM + GRU epilogue ----------------
#define TILE_N 48
#define XS_ULL (TILE_N * 128)

__global__ void __launch_bounds__(256) gemm_kernel(const float* __restrict__ b_gate,
                                                   const float* __restrict__ b_cand,
                                                   float* __restrict__ out_ns) {
    extern __shared__ float smem[];
    float* Ws = smem;                                   // 16384 floats
    ull* xs = (ull*)(smem + 16384);                     // 2 * 6144 ull
    float* bg = (float*)(xs + 2 * XS_ULL);
    float* bc = bg + 64;
    float* pg = bc + 64;
    float* pc = pg + 128;

    int tid = threadIdx.x;
    for (int i = tid; i < 16384 / 4; i += 256)
        ((float4*)Ws)[i] = ((const float4*)g_Wp)[i];
    if (tid < 64) { bg[tid] = b_gate[tid]; bc[tid] = b_cand[tid]; }
    if (tid < 128) { pg[tid] = g_projG[tid]; pc[tid] = g_projC[tid]; }

    int g = tid & 31, p = tid >> 5;
    const int numTiles = (NN + TILE_N - 1) / TILE_N;

    int it0 = blockIdx.x;
    {
        int nb = it0 * TILE_N;
        for (int c = tid; c < TILE_N * 64; c += 256) {
            int node = nb + (c >> 6);
            int off = c & 63;
            int nn = node < NN ? node : 0;
            cpa16((char*)xs + (size_t)c * 16,
                  (const char*)(g_xpair + (size_t)nn * 256) + off * 16);
        }
    }
    asm volatile("cp.async.commit_group;" ::: "memory");

    int ib = 0;
    for (int it = it0; it < numTiles; it += gridDim.x, ib ^= 1) {
        asm volatile("cp.async.wait_group 0;" ::: "memory");
        __syncthreads();
        int nxt = it + gridDim.x;
        if (nxt < numTiles) {
            ull* dstb = xs + (ib ^ 1) * XS_ULL;
            int nb = nxt * TILE_N;
            for (int c = tid; c < TILE_N * 64; c += 256) {
                int node = nb + (c >> 6);
                int off = c & 63;
                int nn = node < NN ? node : 0;
                cpa16((char*)dstb + (size_t)c * 16,
                      (const char*)(g_xpair + (size_t)nn * 256) + off * 16);
            }
        }
        asm volatile("cp.async.commit_group;" ::: "memory");

        ull* xb = xs + ib * XS_ULL;
        const ull* xr0 = xb + (p * 6 + 0) * 128;
        const ull* xr1 = xb + (p * 6 + 1) * 128;
        const ull* xr2 = xb + (p * 6 + 2) * 128;
        const ull* xr3 = xb + (p * 6 + 3) * 128;
        const ull* xr4 = xb + (p * 6 + 4) * 128;
        const ull* xr5 = xb + (p * 6 + 5) * 128;

        ull acc[6][4];
#pragma unroll
        for (int m = 0; m < 6; m++)
#pragma unroll
            for (int c = 0; c < 4; c++) acc[m][c] = 0ull;

#pragma unroll 4
        for (int k = 0; k < 128; k++) {
            float4 w = ((const float4*)(Ws + k * 128))[g];
            ull w0 = splat2(w.x), w1 = splat2(w.y), w2 = splat2(w.z), w3 = splat2(w.w);
            ull x0 = xr0[k], x1 = xr1[k], x2 = xr2[k],
                x3 = xr3[k], x4 = xr4[k], x5 = xr5[k];
            fma2(acc[0][0], w0, x0); fma2(acc[0][1], w1, x0); fma2(acc[0][2], w2, x0); fma2(acc[0][3], w3, x0);
            fma2(acc[1][0], w0, x1); fma2(acc[1][1], w1, x1); fma2(acc[1][2], w2, x1); fma2(acc[1][3], w3, x1);
            fma2(acc[2][0], w0, x2); fma2(acc[2][1], w1, x2); fma2(acc[2][2], w2, x2); fma2(acc[2][3], w3, x2);
            fma2(acc[3][0], w0, x3); fma2(acc[3][1], w1, x3); fma2(acc[3][2], w2, x3); fma2(acc[3][3], w3, x3);
            fma2(acc[4][0], w0, x4); fma2(acc[4][1], w1, x4); fma2(acc[4][2], w2, x4); fma2(acc[4][3], w3, x4);
            fma2(acc[5][0], w0, x5); fma2(acc[5][1], w1, x5); fma2(acc[5][2], w2, x5); fma2(acc[5][3], w3, x5);
        }

        int nb = it * TILE_N;
        const ull* xrs[6] = {xr0, xr1, xr2, xr3, xr4, xr5};
#pragma unroll
        for (int m = 0; m < 6; m++) {
            ull o0 = __shfl_xor_sync(0xffffffffu, acc[m][0], 16);
            ull o1 = __shfl_xor_sync(0xffffffffu, acc[m][1], 16);
            ull o2 = __shfl_xor_sync(0xffffffffu, acc[m][2], 16);
            ull o3 = __shfl_xor_sync(0xffffffffu, acc[m][3], 16);
            int n = nb + p * 6 + m;
            if (g < 16 && n < NN) {
                int fl = g_flag[n];
                ull zacc[4] = {acc[m][0], acc[m][1], acc[m][2], acc[m][3]};
                ull cacc[4] = {o0, o1, o2, o3};
                float4 r0, r1;
                float* q0 = (float*)&r0;
                float* q1 = (float*)&r1;
#pragma unroll
                for (int c = 0; c < 4; c++) {
                    int col = 4 * g + c;
                    float2 zp = u2f2(zacc[c]);
                    float2 cp = u2f2(cacc[c]);
                    float2 sp = u2f2(xrs[m][col]);
                    float zb0 = zp.x + bg[col] + (fl ? pg[col] : 0.f);
                    float zb1 = zp.y + bg[col] + (fl ? pg[64 + col] : 0.f);
                    float cb0 = cp.x + bc[col] + (fl ? pc[col] : 0.f);
                    float cb1 = cp.y + bc[col] + (fl ? pc[64 + col] : 0.f);
                    float z0 = __fdividef(1.f, 1.f + __expf(-zb0));
                    float z1 = __fdividef(1.f, 1.f + __expf(-zb1));
                    float t0 = 1.f - __fdividef(2.f, __expf(2.f * cb0) + 1.f);
                    float t1 = 1.f - __fdividef(2.f, __expf(2.f * cb1) + 1.f);
                    q0[c] = fmaf(z0, t0 - sp.x, sp.x);
                    q1[c] = fmaf(z1, t1 - sp.y, sp.y);
                }
                *((float4*)(out_ns + (size_t)n * 64 + 4 * g)) = r0;
                *((float4*)(out_ns + ((size_t)NN + n) * 64 + 4 * g)) = r1;
            }
        }
        __syncwarp();
    }
}

// ---------------- K4: readout + policy heads ----------------
__global__ void readout_kernel(const float* __restrict__ ns,
                               const int* __restrict__ efferent_idx,
                               const float* __restrict__ W_dec,
                               const float* __restrict__ b_dec,
                               const float* __restrict__ W_mean,
                               const float* __restrict__ b_mean,
                               const float* __restrict__ W_ls,
                               const float* __restrict__ b_ls,
                               float* __restrict__ out) {
    __shared__ float ro[NB * HH];
    __shared__ float dec[NB * HH];
    int t = threadIdx.x;
    int b = t >> 6, h = t & 63;
    float sum = 0.f;
    for (int i = 0; i < NEFF; i++) {
        int idx = efferent_idx[i];
        sum += ns[((size_t)b * NN + idx) * HH + h];
    }
    ro[b * HH + h] = sum * (1.f / NEFF);
    __syncthreads();
    float acc = b_dec[h];
    for (int k = 0; k < HH; k++)
        acc += ro[b * HH + k] * W_dec[k * HH + h];
    dec[b * HH + h] = tanhf(acc);
    __syncthreads();
    if (t < NB * NA) {
        int bb = t / NA, a = t % NA;
        float m = b_mean[a], ls = b_ls[a];
        for (int k = 0; k < HH; k++) {
            float d = dec[bb * HH + k];
            m  += d * W_mean[k * NA + a];
            ls += d * W_ls[k * NA + a];
        }
        ls = fminf(fmaxf(ls, -5.f), 2.f);
        out[bb * NA + a] = m;
        out[NB * NA + bb * NA + a] = ls;
    }
}

// ---------------- launch ----------------
extern "C" void kernel_launch(void* const* d_in, const int* in_sizes, int n_in,
                              void* d_out, int out_size) {
    const float* obs    = (const float*)d_in[0];
    const float* state  = (const float*)d_in[1];
    const float* W_in   = (const float*)d_in[2];
    const float* b_in   = (const float*)d_in[3];
    const float* W_msg  = (const float*)d_in[4];
    const float* W_gate = (const float*)d_in[5];
    const float* b_gate = (const float*)d_in[6];
    const float* W_cand = (const float*)d_in[7];
    const float* b_cand = (const float*)d_in[8];
    const float* W_dec  = (const float*)d_in[9];
    const float* b_dec  = (const float*)d_in[10];
    const float* W_mean = (const float*)d_in[11];
    const float* b_mean = (const float*)d_in[12];
    const float* W_ls   = (const float*)d_in[13];
    const float* b_ls   = (const float*)d_in[14];
    const int* src_idx  = (const int*)d_in[15];
    const int* dst_idx  = (const int*)d_in[16];
    const int* aff_idx  = (const int*)d_in[17];
    const int* eff_idx  = (const int*)d_in[18];
    float* out = (float*)d_out;
    float* out_ns = out + 2 * NB * NA;

    void *cntp = nullptr, *flagp = nullptr;
    cudaGetSymbolAddress(&cntp, g_cnt);
    cudaGetSymbolAddress(&flagp, g_flag);
    cudaMemsetAsync(cntp, 0, sizeof(int) * NN);
    cudaMemsetAsync(flagp, 0, sizeof(int) * NN);

    prep_small_kernel<<<1, 128>>>(obs, W_in, b_in, W_gate, W_cand, aff_idx);
    prep_W_kernel<<<128, 128>>>(W_msg, W_gate, W_cand);

    hist_kernel<<<(NE / 4 + 255) / 256, 256>>>((const int4*)dst_idx);
    scan_part_kernel<<<PB, 256>>>();
    scan_mid_kernel<<<1, 256>>>();
    scan_final_kernel<<<PB, 256>>>();
    scatter_kernel<<<(NE / 4 + 255) / 256, 256>>>((const int4*)src_idx, (const int4*)dst_idx);
    agg_kernel<<<(NN * 32 + 255) / 256, 256>>>(state);

    size_t smem = 16384u * 4 + 2u * XS_ULL * 8 + 384u * 4;   // 165376 bytes
    cudaFuncSetAttribute(gemm_kernel, cudaFuncAttributeMaxDynamicSharedMemorySize, (int)smem);
    gemm_kernel<<<148, 256, smem>>>(b_gate, b_cand, out_ns);

    readout_kernel<<<1, 128>>>(out_ns, eff_idx, W_dec, b_dec, W_mean, b_mean, W_ls, b_ls, out);
}

// round 5
// speedup vs baseline: 1.3872x; 1.0370x over previous
#include <cuda_runtime.h>
#include <cstdint>
#include <cstdio>

#define NB   2
#define NN   50000
#define HH   64
#define NE   1000000
#define NOBS 128
#define NA   18
#define NAFF 512
#define NEFF 256
#define PB   196

#define NBLK   148
#define WTOT   (NBLK * 8)      // 1184 warps
#define GROUP  6

typedef unsigned long long ull;

// ---------------- device scratch ----------------
__device__ float g_Wp[128 * 128];             // fused weight
__device__ float g_projG[NB * HH];
__device__ float g_projC[NB * HH];
__device__ int   g_flag[NN];
__device__ int   g_cnt[NN];
__device__ int   g_off[NN + 1];
__device__ int   g_cur[NN];
__device__ int   g_esrc[NE];
__device__ int   g_part[256];
__device__ int   g_base[256];

// ---------------- helpers ----------------
__device__ __forceinline__ void fma2(ull& d, ull a, ull b) {
    asm("fma.rn.f32x2 %0, %1, %2, %0;" : "+l"(d) : "l"(a), "l"(b));
}
__device__ __forceinline__ ull splat2(float w) {
    ull r; unsigned u = __float_as_uint(w);
    asm("mov.b64 %0, {%1, %1};" : "=l"(r) : "r"(u));
    return r;
}
__device__ __forceinline__ ull pack2(float a, float b) {
    ull r;
    asm("mov.b64 %0, {%1, %2};" : "=l"(r) : "r"(__float_as_uint(a)), "r"(__float_as_uint(b)));
    return r;
}
__device__ __forceinline__ float2 u2f2(ull v) {
    float2 f;
    f.x = __uint_as_float((unsigned)v);
    f.y = __uint_as_float((unsigned)(v >> 32));
    return f;
}
__device__ __forceinline__ int warp_incl_scan(int v) {
    int lane = threadIdx.x & 31;
#pragma unroll
    for (int d = 1; d < 32; d <<= 1) {
        int t = __shfl_up_sync(0xffffffffu, v, d);
        if (lane >= d) v += t;
    }
    return v;
}
__device__ __forceinline__ float sigm(float x) { return __fdividef(1.f, 1.f + __expf(-x)); }
__device__ __forceinline__ float tanha(float x) { return 1.f - __fdividef(2.f, __expf(2.f * x) + 1.f); }

// ---------------- K1a: projections + flags ----------------
__global__ void prep_small_kernel(const float* __restrict__ obs,
                                  const float* __restrict__ W_in,
                                  const float* __restrict__ b_in,
                                  const float* __restrict__ W_gate,
                                  const float* __restrict__ W_cand,
                                  const int* __restrict__ afferent_idx) {
    __shared__ float proj[NB * HH];
    int t = threadIdx.x;            // 128 threads
    int b = t >> 6, h = t & 63;
    float acc = b_in[h];
    for (int o = 0; o < NOBS; o++)
        acc += obs[b * NOBS + o] * W_in[o * HH + h];
    proj[b * HH + h] = acc;
    __syncthreads();
    float ag = 0.f, ac = 0.f;
    for (int k = 0; k < HH; k++) {
        float p = proj[b * HH + k];
        ag += p * W_gate[(HH + k) * HH + h];
        ac += p * W_cand[(HH + k) * HH + h];
    }
    g_projG[b * HH + h] = ag;
    g_projC[b * HH + h] = ac;
    for (int i = t; i < NAFF; i += 128)
        g_flag[afferent_idx[i]] = 1;
}

// ---------------- K1b: fused weight W' ----------------
__global__ void prep_W_kernel(const float* __restrict__ W_msg,
                              const float* __restrict__ W_gate,
                              const float* __restrict__ W_cand) {
    int c = blockIdx.x;     // output column 0..127
    int k = threadIdx.x;    // input row 0..127
    float w;
    if (k < HH) {
        w = (c < HH) ? W_gate[k * HH + c] : W_cand[k * HH + (c - HH)];
    } else {
        int km = k - HH;
        float acc = 0.f;
        if (c < HH) {
            for (int t = 0; t < HH; t++)
                acc += W_msg[km * HH + t] * W_gate[(HH + t) * HH + c];
        } else {
            for (int t = 0; t < HH; t++)
                acc += W_msg[km * HH + t] * W_cand[(HH + t) * HH + (c - HH)];
        }
        w = acc;
    }
    g_Wp[k * 128 + c] = w;
}

// ---------------- CSR build ----------------
__global__ void hist_kernel(const int4* __restrict__ dst4) {
    int i = blockIdx.x * blockDim.x + threadIdx.x;
    if (i < NE / 4) {
        int4 d = __ldg(dst4 + i);
        atomicAdd(&g_cnt[d.x], 1);
        atomicAdd(&g_cnt[d.y], 1);
        atomicAdd(&g_cnt[d.z], 1);
        atomicAdd(&g_cnt[d.w], 1);
    }
}

__global__ void scan_part_kernel() {       // grid PB, block 256
    int i = blockIdx.x * 256 + threadIdx.x;
    int v = (i < NN) ? g_cnt[i] : 0;
    __shared__ int ws[8];
    int s = v;
#pragma unroll
    for (int d = 16; d > 0; d >>= 1) s += __shfl_down_sync(0xffffffffu, s, d);
    if ((threadIdx.x & 31) == 0) ws[threadIdx.x >> 5] = s;
    __syncthreads();
    if (threadIdx.x == 0) {
        int tot = 0;
        for (int w = 0; w < 8; w++) tot += ws[w];
        g_part[blockIdx.x] = tot;
    }
}

__global__ void scan_mid_kernel() {        // 1 block, 256 threads
    int t = threadIdx.x;
    int lane = t & 31, w = t >> 5;
    int v = (t < PB) ? g_part[t] : 0;
    int inc = warp_incl_scan(v);
    __shared__ int ws[8];
    if (lane == 31) ws[w] = inc;
    __syncthreads();
    if (w == 0) {
        int q = (lane < 8) ? ws[lane] : 0;
        int qi = warp_incl_scan(q);
        if (lane < 8) ws[lane] = qi;
    }
    __syncthreads();
    int base = (w > 0) ? ws[w - 1] : 0;
    g_base[t] = base + inc - v;   // exclusive
}

__global__ void scan_final_kernel() {      // grid PB, block 256
    int i = blockIdx.x * 256 + threadIdx.x;
    int t = threadIdx.x;
    int lane = t & 31, w = t >> 5;
    int v = (i < NN) ? g_cnt[i] : 0;
    int inc = warp_incl_scan(v);
    __shared__ int ws[8];
    if (lane == 31) ws[w] = inc;
    __syncthreads();
    if (w == 0) {
        int q = (lane < 8) ? ws[lane] : 0;
        int qi = warp_incl_scan(q);
        if (lane < 8) ws[lane] = qi;
    }
    __syncthreads();
    int base = (w > 0) ? ws[w - 1] : 0;
    int off = g_base[blockIdx.x] + base + inc - v;
    if (i < NN) { g_off[i] = off; g_cur[i] = off; }
    if (i == 0) g_off[NN] = NE;
}

__global__ void scatter_kernel(const int4* __restrict__ src4,
                               const int4* __restrict__ dst4) {
    int i = blockIdx.x * blockDim.x + threadIdx.x;
    if (i < NE / 4) {
        int4 s = __ldg(src4 + i);
        int4 d = __ldg(dst4 + i);
        g_esrc[atomicAdd(&g_cur[d.x], 1)] = s.x;
        g_esrc[atomicAdd(&g_cur[d.y], 1)] = s.y;
        g_esrc[atomicAdd(&g_cur[d.z], 1)] = s.z;
        g_esrc[atomicAdd(&g_cur[d.w], 1)] = s.w;
    }
}

// ---------------- K2: fused gather + f32x2 GEMM + GRU epilogue ----------------
// Each warp owns GROUP node-pairs: gather edges into private smem x-rows,
// run the 128-k FMA2 tile, activate (all lanes), exchange, blend, store.
__global__ void __launch_bounds__(256, 1) fused_kernel(const float* __restrict__ state,
                                                       const float* __restrict__ b_gate,
                                                       const float* __restrict__ b_cand,
                                                       float* __restrict__ out_ns) {
    extern __shared__ float smem[];
    float* Ws = smem;                        // 16384 floats
    ull* xs = (ull*)(smem + 16384);          // 8 warps * GROUP * 128 ull

    int tid = threadIdx.x;
    for (int i = tid; i < 4096; i += 256)
        ((float4*)Ws)[i] = ((const float4*)g_Wp)[i];
    __syncthreads();

    int warp = tid >> 5, lane = tid & 31;
    int q = lane & 15;
    int cc0 = q * 4;
    bool zside = lane < 16;

    // per-lane bias/proj registers (cols cc0..cc0+3; z-lanes gate, cand-lanes cand)
    float bias[4], pj0[4], pj1[4];
#pragma unroll
    for (int c = 0; c < 4; c++) {
        int cc = cc0 + c;
        if (zside) { bias[c] = __ldg(b_gate + cc); pj0[c] = g_projG[cc]; pj1[c] = g_projG[64 + cc]; }
        else       { bias[c] = __ldg(b_cand + cc); pj0[c] = g_projC[cc]; pj1[c] = g_projC[64 + cc]; }
    }

    ull* mx = xs + warp * (GROUP * 128);
    int gwid = blockIdx.x * 8 + warp;
    const float2* s0 = (const float2*)state;
    const float2* s1 = s0 + (size_t)NN * 32;

    for (int base = gwid * GROUP; base < NN; base += WTOT * GROUP) {
        int cnt = NN - base;
        if (cnt > GROUP) cnt = GROUP;
        int flg[GROUP];

        // ---- gather phase ----
        for (int m = 0; m < cnt; m++) {
            int n = base + m;
            int beg = __ldg(&g_off[n]), end = __ldg(&g_off[n + 1]);
            flg[m] = __ldg(&g_flag[n]);
            float4 acc = make_float4(0.f, 0.f, 0.f, 0.f);
            int j = beg;
            for (; j + 4 <= end; j += 4) {
                int e0 = __ldg(g_esrc + j),     e1 = __ldg(g_esrc + j + 1);
                int e2 = __ldg(g_esrc + j + 2), e3 = __ldg(g_esrc + j + 3);
                float2 a0 = __ldg(s0 + (size_t)e0 * 32 + lane);
                float2 b0 = __ldg(s1 + (size_t)e0 * 32 + lane);
                float2 a1 = __ldg(s0 + (size_t)e1 * 32 + lane);
                float2 b1 = __ldg(s1 + (size_t)e1 * 32 + lane);
                float2 a2 = __ldg(s0 + (size_t)e2 * 32 + lane);
                float2 b2 = __ldg(s1 + (size_t)e2 * 32 + lane);
                float2 a3 = __ldg(s0 + (size_t)e3 * 32 + lane);
                float2 b3 = __ldg(s1 + (size_t)e3 * 32 + lane);
                acc.x += a0.x + a1.x + a2.x + a3.x;
                acc.y += a0.y + a1.y + a2.y + a3.y;
                acc.z += b0.x + b1.x + b2.x + b3.x;
                acc.w += b0.y + b1.y + b2.y + b3.y;
            }
            for (; j < end; j++) {
                int e0 = __ldg(g_esrc + j);
                float2 a = __ldg(s0 + (size_t)e0 * 32 + lane);
                float2 b = __ldg(s1 + (size_t)e0 * 32 + lane);
                acc.x += a.x; acc.y += a.y; acc.z += b.x; acc.w += b.y;
            }
            float2 sa = __ldg(s0 + (size_t)n * 32 + lane);
            float2 sb = __ldg(s1 + (size_t)n * 32 + lane);
            ull* row = mx + m * 128;
            // state half (k=2l,2l+1), agg half (k=64+2l,64+2l+1)
            ((float4*)row)[lane]        = make_float4(sa.x, sb.x, sa.y, sb.y);
            ((float4*)(row + 64))[lane] = make_float4(acc.x, acc.z, acc.y, acc.w);
        }
        __syncwarp();

        // ---- FMA phase ----
        ull acc6[GROUP][4];
#pragma unroll
        for (int m = 0; m < GROUP; m++)
#pragma unroll
            for (int c = 0; c < 4; c++) acc6[m][c] = 0ull;

#pragma unroll 4
        for (int k = 0; k < 128; k += 2) {
            float4 wA = ((const float4*)(Ws + k * 128))[lane];
            float4 wB = ((const float4*)(Ws + (k + 1) * 128))[lane];
            ull wa0 = splat2(wA.x), wa1 = splat2(wA.y), wa2 = splat2(wA.z), wa3 = splat2(wA.w);
            ull wb0 = splat2(wB.x), wb1 = splat2(wB.y), wb2 = splat2(wB.z), wb3 = splat2(wB.w);
#pragma unroll
            for (int m = 0; m < GROUP; m++) {
                ulonglong2 xv = ((const ulonglong2*)(mx + m * 128))[k >> 1];
                fma2(acc6[m][0], wa0, xv.x); fma2(acc6[m][1], wa1, xv.x);
                fma2(acc6[m][2], wa2, xv.x); fma2(acc6[m][3], wa3, xv.x);
                fma2(acc6[m][0], wb0, xv.y); fma2(acc6[m][1], wb1, xv.y);
                fma2(acc6[m][2], wb2, xv.y); fma2(acc6[m][3], wb3, xv.y);
            }
        }

        // ---- epilogue: all lanes activate own side, exchange, z-lanes blend+store ----
        for (int m = 0; m < cnt; m++) {
            int n = base + m;
            ull actp[4];
#pragma unroll
            for (int c = 0; c < 4; c++) {
                float2 pre = u2f2(acc6[m][c]);
                float p0 = pre.x + bias[c] + (flg[m] ? pj0[c] : 0.f);
                float p1 = pre.y + bias[c] + (flg[m] ? pj1[c] : 0.f);
                float a0, a1;
                if (zside) { a0 = sigm(p0);  a1 = sigm(p1); }
                else       { a0 = tanha(p0); a1 = tanha(p1); }
                actp[c] = pack2(a0, a1);
            }
            ull oth[4];
#pragma unroll
            for (int c = 0; c < 4; c++)
                oth[c] = __shfl_xor_sync(0xffffffffu, actp[c], 16);
            if (zside) {
                float4 r0, r1;
                float* q0 = (float*)&r0;
                float* q1 = (float*)&r1;
#pragma unroll
                for (int c = 0; c < 4; c++) {
                    float2 z = u2f2(actp[c]);
                    float2 t = u2f2(oth[c]);
                    float2 sp = u2f2(mx[m * 128 + cc0 + c]);   // cols<64: state pair
                    q0[c] = fmaf(z.x, t.x - sp.x, sp.x);
                    q1[c] = fmaf(z.y, t.y - sp.y, sp.y);
                }
                *((float4*)(out_ns + (size_t)n * 64 + cc0)) = r0;
                *((float4*)(out_ns + ((size_t)NN + n) * 64 + cc0)) = r1;
            }
        }
        __syncwarp();
    }
}

// ---------------- K4: readout + policy heads ----------------
__global__ void readout_kernel(const float* __restrict__ ns,
                               const int* __restrict__ efferent_idx,
                               const float* __restrict__ W_dec,
                               const float* __restrict__ b_dec,
                               const float* __restrict__ W_mean,
                               const float* __restrict__ b_mean,
                               const float* __restrict__ W_ls,
                               const float* __restrict__ b_ls,
                               float* __restrict__ out) {
    __shared__ float ro[NB * HH];
    __shared__ float dec[NB * HH];
    int t = threadIdx.x;
    int b = t >> 6, h = t & 63;
    float sum = 0.f;
    for (int i = 0; i < NEFF; i++) {
        int idx = efferent_idx[i];
        sum += ns[((size_t)b * NN + idx) * HH + h];
    }
    ro[b * HH + h] = sum * (1.f / NEFF);
    __syncthreads();
    float acc = b_dec[h];
    for (int k = 0; k < HH; k++)
        acc += ro[b * HH + k] * W_dec[k * HH + h];
    dec[b * HH + h] = tanhf(acc);
    __syncthreads();
    if (t < NB * NA) {
        int bb = t / NA, a = t % NA;
        float m = b_mean[a], ls = b_ls[a];
        for (int k = 0; k < HH; k++) {
            float d = dec[bb * HH + k];
            m  += d * W_mean[k * NA + a];
            ls += d * W_ls[k * NA + a];
        }
        ls = fminf(fmaxf(ls, -5.f), 2.f);
        out[bb * NA + a] = m;
        out[NB * NA + bb * NA + a] = ls;
    }
}

// ---------------- launch ----------------
extern "C" void kernel_launch(void* const* d_in, const int* in_sizes, int n_in,
                              void* d_out, int out_size) {
    const float* obs    = (const float*)d_in[0];
    const float* state  = (const float*)d_in[1];
    const float* W_in   = (const float*)d_in[2];
    const float* b_in   = (const float*)d_in[3];
    const float* W_msg  = (const float*)d_in[4];
    const float* W_gate = (const float*)d_in[5];
    const float* b_gate = (const float*)d_in[6];
    const float* W_cand = (const float*)d_in[7];
    const float* b_cand = (const float*)d_in[8];
    const float* W_dec  = (const float*)d_in[9];
    const float* b_dec  = (const float*)d_in[10];
    const float* W_mean = (const float*)d_in[11];
    const float* b_mean = (const float*)d_in[12];
    const float* W_ls   = (const float*)d_in[13];
    const float* b_ls   = (const float*)d_in[14];
    const int* src_idx  = (const int*)d_in[15];
    const int* dst_idx  = (const int*)d_in[16];
    const int* aff_idx  = (const int*)d_in[17];
    const int* eff_idx  = (const int*)d_in[18];
    float* out = (float*)d_out;
    float* out_ns = out + 2 * NB * NA;

    void *cntp = nullptr, *flagp = nullptr;
    cudaGetSymbolAddress(&cntp, g_cnt);
    cudaGetSymbolAddress(&flagp, g_flag);
    cudaMemsetAsync(cntp, 0, sizeof(int) * NN);
    cudaMemsetAsync(flagp, 0, sizeof(int) * NN);

    prep_small_kernel<<<1, 128>>>(obs, W_in, b_in, W_gate, W_cand, aff_idx);
    prep_W_kernel<<<128, 128>>>(W_msg, W_gate, W_cand);

    hist_kernel<<<(NE / 4 + 255) / 256, 256>>>((const int4*)dst_idx);
    scan_part_kernel<<<PB, 256>>>();
    scan_mid_kernel<<<1, 256>>>();
    scan_final_kernel<<<PB, 256>>>();
    scatter_kernel<<<(NE / 4 + 255) / 256, 256>>>((const int4*)src_idx, (const int4*)dst_idx);

    size_t smem = 16384u * 4 + 8u * GROUP * 128 * 8;   // 64KB + 48KB = 114688
    cudaFuncSetAttribute(fused_kernel, cudaFuncAttributeMaxDynamicSharedMemorySize, (int)smem);
    fused_kernel<<<NBLK, 256, smem>>>(state, b_gate, b_cand, out_ns);

    readout_kernel<<<1, 128>>>(out_ns, eff_idx, W_dec, b_dec, W_mean, b_mean, W_ls, b_ls, out);
}

// round 6
// speedup vs baseline: 1.7179x; 1.2384x over previous
#include <cuda_runtime.h>
#include <cstdint>
#include <cstdio>

#define NB   2
#define NN   50000
#define HH   64
#define NE   1000000
#define NOBS 128
#define NA   18
#define NAFF 512
#define NEFF 256
#define PB   196

#define NBLK   148
#define NW     16
#define WTOT   (NBLK * NW)     // 2368 warps
#define GROUP  6
#define WIN    512             // idx window (ints) per warp

typedef unsigned long long ull;

// ---------------- device scratch ----------------
__device__ float g_Wp[128 * 128];             // fused weight
__device__ float g_projG[NB * HH];
__device__ float g_projC[NB * HH];
__device__ int   g_flag[NN];
__device__ int   g_cnt[NN];
__device__ int   g_off[NN + 1];
__device__ int   g_cur[NN];
__device__ int   g_esrc[NE + WIN];            // padded for cp.async overread
__device__ int   g_part[256];
__device__ int   g_base[256];

// ---------------- helpers ----------------
__device__ __forceinline__ void fma2(ull& d, ull a, ull b) {
    asm("fma.rn.f32x2 %0, %1, %2, %0;" : "+l"(d) : "l"(a), "l"(b));
}
__device__ __forceinline__ ull splat2(float w) {
    ull r; unsigned u = __float_as_uint(w);
    asm("mov.b64 %0, {%1, %1};" : "=l"(r) : "r"(u));
    return r;
}
__device__ __forceinline__ ull pack2(float a, float b) {
    ull r;
    asm("mov.b64 %0, {%1, %2};" : "=l"(r) : "r"(__float_as_uint(a)), "r"(__float_as_uint(b)));
    return r;
}
__device__ __forceinline__ float2 u2f2(ull v) {
    float2 f;
    f.x = __uint_as_float((unsigned)v);
    f.y = __uint_as_float((unsigned)(v >> 32));
    return f;
}
__device__ __forceinline__ void cpa16(void* dst, const void* src) {
    unsigned d = (unsigned)__cvta_generic_to_shared(dst);
    asm volatile("cp.async.cg.shared.global [%0], [%1], 16;" :: "r"(d), "l"(src));
}
__device__ __forceinline__ int warp_incl_scan(int v) {
    int lane = threadIdx.x & 31;
#pragma unroll
    for (int d = 1; d < 32; d <<= 1) {
        int t = __shfl_up_sync(0xffffffffu, v, d);
        if (lane >= d) v += t;
    }
    return v;
}
__device__ __forceinline__ float sigm(float x) { return __fdividef(1.f, 1.f + __expf(-x)); }
__device__ __forceinline__ float tanha(float x) { return 1.f - __fdividef(2.f, __expf(2.f * x) + 1.f); }

// ---------------- K1a: projections + flags ----------------
__global__ void prep_small_kernel(const float* __restrict__ obs,
                                  const float* __restrict__ W_in,
                                  const float* __restrict__ b_in,
                                  const float* __restrict__ W_gate,
                                  const float* __restrict__ W_cand,
                                  const int* __restrict__ afferent_idx) {
    __shared__ float proj[NB * HH];
    int t = threadIdx.x;            // 128 threads
    int b = t >> 6, h = t & 63;
    float acc = b_in[h];
    for (int o = 0; o < NOBS; o++)
        acc += obs[b * NOBS + o] * W_in[o * HH + h];
    proj[b * HH + h] = acc;
    __syncthreads();
    float ag = 0.f, ac = 0.f;
    for (int k = 0; k < HH; k++) {
        float p = proj[b * HH + k];
        ag += p * W_gate[(HH + k) * HH + h];
        ac += p * W_cand[(HH + k) * HH + h];
    }
    g_projG[b * HH + h] = ag;
    g_projC[b * HH + h] = ac;
    for (int i = t; i < NAFF; i += 128)
        g_flag[afferent_idx[i]] = 1;
}

// ---------------- K1b: fused weight W' ----------------
__global__ void prep_W_kernel(const float* __restrict__ W_msg,
                              const float* __restrict__ W_gate,
                              const float* __restrict__ W_cand) {
    int c = blockIdx.x;     // output column 0..127
    int k = threadIdx.x;    // input row 0..127
    float w;
    if (k < HH) {
        w = (c < HH) ? W_gate[k * HH + c] : W_cand[k * HH + (c - HH)];
    } else {
        int km = k - HH;
        float acc = 0.f;
        if (c < HH) {
            for (int t = 0; t < HH; t++)
                acc += W_msg[km * HH + t] * W_gate[(HH + t) * HH + c];
        } else {
            for (int t = 0; t < HH; t++)
                acc += W_msg[km * HH + t] * W_cand[(HH + t) * HH + (c - HH)];
        }
        w = acc;
    }
    g_Wp[k * 128 + c] = w;
}

// ---------------- CSR build ----------------
__global__ void hist_kernel(const int4* __restrict__ dst4) {
    int i = blockIdx.x * blockDim.x + threadIdx.x;
    if (i < NE / 4) {
        int4 d = __ldg(dst4 + i);
        atomicAdd(&g_cnt[d.x], 1);
        atomicAdd(&g_cnt[d.y], 1);
        atomicAdd(&g_cnt[d.z], 1);
        atomicAdd(&g_cnt[d.w], 1);
    }
}

__global__ void scan_part_kernel() {       // grid PB, block 256
    int i = blockIdx.x * 256 + threadIdx.x;
    int v = (i < NN) ? g_cnt[i] : 0;
    __shared__ int ws[8];
    int s = v;
#pragma unroll
    for (int d = 16; d > 0; d >>= 1) s += __shfl_down_sync(0xffffffffu, s, d);
    if ((threadIdx.x & 31) == 0) ws[threadIdx.x >> 5] = s;
    __syncthreads();
    if (threadIdx.x == 0) {
        int tot = 0;
        for (int w = 0; w < 8; w++) tot += ws[w];
        g_part[blockIdx.x] = tot;
    }
}

__global__ void scan_mid_kernel() {        // 1 block, 256 threads
    int t = threadIdx.x;
    int lane = t & 31, w = t >> 5;
    int v = (t < PB) ? g_part[t] : 0;
    int inc = warp_incl_scan(v);
    __shared__ int ws[8];
    if (lane == 31) ws[w] = inc;
    __syncthreads();
    if (w == 0) {
        int q = (lane < 8) ? ws[lane] : 0;
        int qi = warp_incl_scan(q);
        if (lane < 8) ws[lane] = qi;
    }
    __syncthreads();
    int base = (w > 0) ? ws[w - 1] : 0;
    g_base[t] = base + inc - v;   // exclusive
}

__global__ void scan_final_kernel() {      // grid PB, block 256
    int i = blockIdx.x * 256 + threadIdx.x;
    int t = threadIdx.x;
    int lane = t & 31, w = t >> 5;
    int v = (i < NN) ? g_cnt[i] : 0;
    int inc = warp_incl_scan(v);
    __shared__ int ws[8];
    if (lane == 31) ws[w] = inc;
    __syncthreads();
    if (w == 0) {
        int q = (lane < 8) ? ws[lane] : 0;
        int qi = warp_incl_scan(q);
        if (lane < 8) ws[lane] = qi;
    }
    __syncthreads();
    int base = (w > 0) ? ws[w - 1] : 0;
    int off = g_base[blockIdx.x] + base + inc - v;
    if (i < NN) { g_off[i] = off; g_cur[i] = off; }
    if (i == 0) g_off[NN] = NE;
}

__global__ void scatter_kernel(const int4* __restrict__ src4,
                               const int4* __restrict__ dst4) {
    int i = blockIdx.x * blockDim.x + threadIdx.x;
    if (i < NE / 4) {
        int4 s = __ldg(src4 + i);
        int4 d = __ldg(dst4 + i);
        g_esrc[atomicAdd(&g_cur[d.x], 1)] = s.x;
        g_esrc[atomicAdd(&g_cur[d.y], 1)] = s.y;
        g_esrc[atomicAdd(&g_cur[d.z], 1)] = s.z;
        g_esrc[atomicAdd(&g_cur[d.w], 1)] = s.w;
    }
}

// ---------------- K2: fused gather + f32x2 GEMM + GRU epilogue ----------------
// 16 warps/block, 1 block/SM. Each warp owns GROUP nodes; its CSR edge slab is
// contiguous -> staged into smem via cp.async so the gather loop has no
// index-load dependency. No block syncs in the main loop: warps interleave
// gather (LTS) with FMA (fma pipe) naturally.
__global__ void __launch_bounds__(512, 1) fused_kernel(const float* __restrict__ state,
                                                       const float* __restrict__ b_gate,
                                                       const float* __restrict__ b_cand,
                                                       float* __restrict__ out_ns) {
    extern __shared__ float smem[];
    float* Ws = smem;                                    // 16384 floats
    ull* xs = (ull*)(smem + 16384);                      // NW * GROUP * 128 ull
    int* sIdx = (int*)(xs + NW * GROUP * 128);           // NW * WIN ints

    int tid = threadIdx.x;
    for (int i = tid; i < 4096; i += 512)
        ((float4*)Ws)[i] = ((const float4*)g_Wp)[i];
    __syncthreads();

    int warp = tid >> 5, lane = tid & 31;
    int q = lane & 15;
    int cc0 = q * 4;
    bool zside = lane < 16;

    float bias[4], pj0[4], pj1[4];
#pragma unroll
    for (int c = 0; c < 4; c++) {
        int cc = cc0 + c;
        if (zside) { bias[c] = __ldg(b_gate + cc); pj0[c] = g_projG[cc]; pj1[c] = g_projG[64 + cc]; }
        else       { bias[c] = __ldg(b_cand + cc); pj0[c] = g_projC[cc]; pj1[c] = g_projC[64 + cc]; }
    }

    ull* mx = xs + warp * (GROUP * 128);
    int* widx = sIdx + warp * WIN;
    int gwid = blockIdx.x * NW + warp;
    const float2* s0 = (const float2*)state;
    const float2* s1 = s0 + (size_t)NN * 32;

    for (int base = gwid * GROUP; base < NN; base += WTOT * GROUP) {
        int cnt = NN - base;
        if (cnt > GROUP) cnt = GROUP;
        int flg[GROUP];

        // ---- stage index slab (contiguous CSR range for this group) ----
        int slab = __ldg(&g_off[base]) & ~3;    // 16B-aligned window start
        for (int c = lane; c < WIN / 4; c += 32)
            cpa16(widx + c * 4, g_esrc + slab + c * 4);
        asm volatile("cp.async.commit_group;" ::: "memory");
        asm volatile("cp.async.wait_group 0;" ::: "memory");
        __syncwarp();

        // ---- gather phase ----
        for (int m = 0; m < cnt; m++) {
            int n = base + m;
            int beg = __ldg(&g_off[n]), end = __ldg(&g_off[n + 1]);
            flg[m] = __ldg(&g_flag[n]);
            float4 acc = make_float4(0.f, 0.f, 0.f, 0.f);
            int j = beg;
            while (j < end) {
                if (j >= slab + WIN) {           // refill window (rare)
                    slab = j & ~3;
                    for (int c = lane; c < WIN / 4; c += 32)
                        cpa16(widx + c * 4, g_esrc + slab + c * 4);
                    asm volatile("cp.async.commit_group;" ::: "memory");
                    asm volatile("cp.async.wait_group 0;" ::: "memory");
                    __syncwarp();
                }
                int lim = slab + WIN;
                if (lim > end) lim = end;
                for (; j + 4 <= lim; j += 4) {
                    int e0 = widx[j - slab],     e1 = widx[j - slab + 1];
                    int e2 = widx[j - slab + 2], e3 = widx[j - slab + 3];
                    float2 a0 = __ldg(s0 + (size_t)e0 * 32 + lane);
                    float2 b0 = __ldg(s1 + (size_t)e0 * 32 + lane);
                    float2 a1 = __ldg(s0 + (size_t)e1 * 32 + lane);
                    float2 b1 = __ldg(s1 + (size_t)e1 * 32 + lane);
                    float2 a2 = __ldg(s0 + (size_t)e2 * 32 + lane);
                    float2 b2 = __ldg(s1 + (size_t)e2 * 32 + lane);
                    float2 a3 = __ldg(s0 + (size_t)e3 * 32 + lane);
                    float2 b3 = __ldg(s1 + (size_t)e3 * 32 + lane);
                    acc.x += a0.x + a1.x + a2.x + a3.x;
                    acc.y += a0.y + a1.y + a2.y + a3.y;
                    acc.z += b0.x + b1.x + b2.x + b3.x;
                    acc.w += b0.y + b1.y + b2.y + b3.y;
                }
                for (; j < lim; j++) {
                    int e0 = widx[j - slab];
                    float2 a = __ldg(s0 + (size_t)e0 * 32 + lane);
                    float2 b = __ldg(s1 + (size_t)e0 * 32 + lane);
                    acc.x += a.x; acc.y += a.y; acc.z += b.x; acc.w += b.y;
                }
            }
            float2 sa = __ldg(s0 + (size_t)n * 32 + lane);
            float2 sb = __ldg(s1 + (size_t)n * 32 + lane);
            ull* row = mx + m * 128;
            ((float4*)row)[lane]        = make_float4(sa.x, sb.x, sa.y, sb.y);
            ((float4*)(row + 64))[lane] = make_float4(acc.x, acc.z, acc.y, acc.w);
        }
        __syncwarp();

        // ---- FMA phase ----
        ull acc6[GROUP][4];
#pragma unroll
        for (int m = 0; m < GROUP; m++)
#pragma unroll
            for (int c = 0; c < 4; c++) acc6[m][c] = 0ull;

#pragma unroll 4
        for (int k = 0; k < 128; k += 2) {
            float4 wA = ((const float4*)(Ws + k * 128))[lane];
            float4 wB = ((const float4*)(Ws + (k + 1) * 128))[lane];
            ull wa0 = splat2(wA.x), wa1 = splat2(wA.y), wa2 = splat2(wA.z), wa3 = splat2(wA.w);
            ull wb0 = splat2(wB.x), wb1 = splat2(wB.y), wb2 = splat2(wB.z), wb3 = splat2(wB.w);
#pragma unroll
            for (int m = 0; m < GROUP; m++) {
                ulonglong2 xv = ((const ulonglong2*)(mx + m * 128))[k >> 1];
                fma2(acc6[m][0], wa0, xv.x); fma2(acc6[m][1], wa1, xv.x);
                fma2(acc6[m][2], wa2, xv.x); fma2(acc6[m][3], wa3, xv.x);
                fma2(acc6[m][0], wb0, xv.y); fma2(acc6[m][1], wb1, xv.y);
                fma2(acc6[m][2], wb2, xv.y); fma2(acc6[m][3], wb3, xv.y);
            }
        }

        // ---- epilogue ----
        for (int m = 0; m < cnt; m++) {
            int n = base + m;
            ull actp[4];
#pragma unroll
            for (int c = 0; c < 4; c++) {
                float2 pre = u2f2(acc6[m][c]);
                float p0 = pre.x + bias[c] + (flg[m] ? pj0[c] : 0.f);
                float p1 = pre.y + bias[c] + (flg[m] ? pj1[c] : 0.f);
                float a0, a1;
                if (zside) { a0 = sigm(p0);  a1 = sigm(p1); }
                else       { a0 = tanha(p0); a1 = tanha(p1); }
                actp[c] = pack2(a0, a1);
            }
            ull oth[4];
#pragma unroll
            for (int c = 0; c < 4; c++)
                oth[c] = __shfl_xor_sync(0xffffffffu, actp[c], 16);
            if (zside) {
                float4 r0, r1;
                float* q0 = (float*)&r0;
                float* q1 = (float*)&r1;
#pragma unroll
                for (int c = 0; c < 4; c++) {
                    float2 z = u2f2(actp[c]);
                    float2 t = u2f2(oth[c]);
                    float2 sp = u2f2(mx[m * 128 + cc0 + c]);
                    q0[c] = fmaf(z.x, t.x - sp.x, sp.x);
                    q1[c] = fmaf(z.y, t.y - sp.y, sp.y);
                }
                *((float4*)(out_ns + (size_t)n * 64 + cc0)) = r0;
                *((float4*)(out_ns + ((size_t)NN + n) * 64 + cc0)) = r1;
            }
        }
        __syncwarp();
    }
}

// ---------------- K4: readout + policy heads ----------------
__global__ void readout_kernel(const float* __restrict__ ns,
                               const int* __restrict__ efferent_idx,
                               const float* __restrict__ W_dec,
                               const float* __restrict__ b_dec,
                               const float* __restrict__ W_mean,
                               const float* __restrict__ b_mean,
                               const float* __restrict__ W_ls,
                               const float* __restrict__ b_ls,
                               float* __restrict__ out) {
    __shared__ float ro[NB * HH];
    __shared__ float dec[NB * HH];
    int t = threadIdx.x;
    int b = t >> 6, h = t & 63;
    float sum = 0.f;
    for (int i = 0; i < NEFF; i++) {
        int idx = efferent_idx[i];
        sum += ns[((size_t)b * NN + idx) * HH + h];
    }
    ro[b * HH + h] = sum * (1.f / NEFF);
    __syncthreads();
    float acc = b_dec[h];
    for (int k = 0; k < HH; k++)
        acc += ro[b * HH + k] * W_dec[k * HH + h];
    dec[b * HH + h] = tanhf(acc);
    __syncthreads();
    if (t < NB * NA) {
        int bb = t / NA, a = t % NA;
        float m = b_mean[a], ls = b_ls[a];
        for (int k = 0; k < HH; k++) {
            float d = dec[bb * HH + k];
            m  += d * W_mean[k * NA + a];
            ls += d * W_ls[k * NA + a];
        }
        ls = fminf(fmaxf(ls, -5.f), 2.f);
        out[bb * NA + a] = m;
        out[NB * NA + bb * NA + a] = ls;
    }
}

// ---------------- launch ----------------
extern "C" void kernel_launch(void* const* d_in, const int* in_sizes, int n_in,
                              void* d_out, int out_size) {
    const float* obs    = (const float*)d_in[0];
    const float* state  = (const float*)d_in[1];
    const float* W_in   = (const float*)d_in[2];
    const float* b_in   = (const float*)d_in[3];
    const float* W_msg  = (const float*)d_in[4];
    const float* W_gate = (const float*)d_in[5];
    const float* b_gate = (const float*)d_in[6];
    const float* W_cand = (const float*)d_in[7];
    const float* b_cand = (const float*)d_in[8];
    const float* W_dec  = (const float*)d_in[9];
    const float* b_dec  = (const float*)d_in[10];
    const float* W_mean = (const float*)d_in[11];
    const float* b_mean = (const float*)d_in[12];
    const float* W_ls   = (const float*)d_in[13];
    const float* b_ls   = (const float*)d_in[14];
    const int* src_idx  = (const int*)d_in[15];
    const int* dst_idx  = (const int*)d_in[16];
    const int* aff_idx  = (const int*)d_in[17];
    const int* eff_idx  = (const int*)d_in[18];
    float* out = (float*)d_out;
    float* out_ns = out + 2 * NB * NA;

    void *cntp = nullptr, *flagp = nullptr;
    cudaGetSymbolAddress(&cntp, g_cnt);
    cudaGetSymbolAddress(&flagp, g_flag);
    cudaMemsetAsync(cntp, 0, sizeof(int) * NN);
    cudaMemsetAsync(flagp, 0, sizeof(int) * NN);

    prep_small_kernel<<<1, 128>>>(obs, W_in, b_in, W_gate, W_cand, aff_idx);
    prep_W_kernel<<<128, 128>>>(W_msg, W_gate, W_cand);

    hist_kernel<<<(NE / 4 + 255) / 256, 256>>>((const int4*)dst_idx);
    scan_part_kernel<<<PB, 256>>>();
    scan_mid_kernel<<<1, 256>>>();
    scan_final_kernel<<<PB, 256>>>();
    scatter_kernel<<<(NE / 4 + 255) / 256, 256>>>((const int4*)src_idx, (const int4*)dst_idx);

    size_t smem = 16384u * 4 + (size_t)NW * GROUP * 128 * 8 + (size_t)NW * WIN * 4;  // 196608
    cudaFuncSetAttribute(fused_kernel, cudaFuncAttributeMaxDynamicSharedMemorySize, (int)smem);
    fused_kernel<<<NBLK, 512, smem>>>(state, b_gate, b_cand, out_ns);

    readout_kernel<<<1, 128>>>(out_ns, eff_idx, W_dec, b_dec, W_mean, b_mean, W_ls, b_ls, out);
}